// round 12
// baseline (speedup 1.0000x reference)
#include <cuda_runtime.h>
#include <cuda_bf16.h>
#include <math.h>
#include <stdint.h>

#define BB 512
#define TT 168
#define HH 512
#define GG 2048   // 4*H
#define WD 4
#define BH (BB*HH)
#define NCTA 128

// ---------------- device scratch ----------------
__device__ __align__(256) __nv_bfloat16 g_h1h[TT*BH];
__device__ __align__(256) __nv_bfloat16 g_h1l[TT*BH];
__device__ __align__(256) __nv_bfloat16 g_h2h[TT*BH];
__device__ __align__(256) __nv_bfloat16 g_h2l[TT*BH];

// transposed + gate-interleaved weights, layout [n=2048][k=512] bf16 (hi/lo)
__device__ __align__(256) __nv_bfloat16 g_U1h[GG*HH], g_U1l[GG*HH];
__device__ __align__(256) __nv_bfloat16 g_U2h[GG*HH], g_U2l[GG*HH];
__device__ __align__(256) __nv_bfloat16 g_W2h[GG*HH], g_W2l[GG*HH];
__device__ float g_b1p[GG], g_b2p[GG], g_W1p[GG], g_V1p[WD*GG], g_V2p[WD*GG];
__device__ unsigned g_bar;

// ---------------- helpers ----------------
__device__ __forceinline__ uint32_t s2u(const void* p) {
    uint32_t a;
    asm("{ .reg .u64 t; cvta.to.shared.u64 t, %1; cvt.u32.u64 %0, t; }" : "=r"(a) : "l"(p));
    return a;
}
__device__ __forceinline__ void cpasync16(uint32_t dst, const void* src) {
    asm volatile("cp.async.cg.shared.global [%0], [%1], 16;" :: "r"(dst), "l"(src));
}
#define CP_COMMIT() asm volatile("cp.async.commit_group;")
#define CP_WAIT(n)  asm volatile("cp.async.wait_group %0;" :: "n"(n))
#define LDSM4(r0,r1,r2,r3,addr) \
    asm volatile("ldmatrix.sync.aligned.m8n8.x4.shared.b16 {%0,%1,%2,%3}, [%4];" \
        : "=r"(r0),"=r"(r1),"=r"(r2),"=r"(r3) : "r"(addr))

__device__ __forceinline__ void mma16816(float* c, const uint32_t* a, uint32_t b0, uint32_t b1) {
    asm volatile("mma.sync.aligned.m16n8k16.row.col.f32.bf16.bf16.f32 "
        "{%0,%1,%2,%3}, {%4,%5,%6,%7}, {%8,%9}, {%0,%1,%2,%3};"
        : "+f"(c[0]), "+f"(c[1]), "+f"(c[2]), "+f"(c[3])
        : "r"(a[0]), "r"(a[1]), "r"(a[2]), "r"(a[3]), "r"(b0), "r"(b1));
}

__device__ __forceinline__ float sigf(float x) { return 1.0f / (1.0f + __expf(-x)); }
__device__ __forceinline__ float tanhfast(float x) { return 1.0f - 2.0f / (1.0f + __expf(2.0f * x)); }

// ---------------- prologue: permute + transpose + bf16 hi/lo split ----------------
__global__ void prep_kernel(const float* __restrict__ W1, const float* __restrict__ U1,
                            const float* __restrict__ V1, const float* __restrict__ b1,
                            const float* __restrict__ W2, const float* __restrict__ U2,
                            const float* __restrict__ V2, const float* __restrict__ b2) {
    int idx = blockIdx.x * blockDim.x + threadIdx.x;
    if (idx == 0) g_bar = 0u;
    if (idx >= HH * GG) return;
    int k  = idx >> 11;
    int gp = idx & (GG - 1);
    int go = (gp & 3) * HH + (gp >> 2);
    int dst = gp * HH + k;

    float u1 = U1[k * GG + go];
    __nv_bfloat16 h = __float2bfloat16(u1);
    g_U1h[dst] = h; g_U1l[dst] = __float2bfloat16(u1 - __bfloat162float(h));
    float u2 = U2[k * GG + go];
    h = __float2bfloat16(u2);
    g_U2h[dst] = h; g_U2l[dst] = __float2bfloat16(u2 - __bfloat162float(h));
    float w2 = W2[k * GG + go];
    h = __float2bfloat16(w2);
    g_W2h[dst] = h; g_W2l[dst] = __float2bfloat16(w2 - __bfloat162float(h));

    if (k == 0) {
        g_W1p[gp] = W1[go];
        g_b1p[gp] = b1[go];
        g_b2p[gp] = b2[go];
#pragma unroll
        for (int w = 0; w < WD; w++) {
            g_V1p[w * GG + gp] = V1[w * GG + go];
            g_V2p[w * GG + gp] = V2[w * GG + go];
        }
    }
}

// ---------------- persistent wavefront LSTM kernel ----------------
// CTA tile M=128 (batch) x N=64 (gates), BK=64. Grid (32, 4) = 128 CTAs, 128 threads.
// Interval w: L1 computes t=w, L2 computes t=w-1 (wavefront pipelining).
#define NS 3
#define OA_H 0
#define OA_L 16384
#define OB_H 32768
#define OB_L 40960
#define STAGE_BYTES 49152
#define SP1_OFF 0
#define SP2_OFF 2048
#define GS_OFF 4096
#define GSP 68
#define STG_OFF2 38912                       // 4096 + 128*68*4
#define SMEM_TOTAL (STG_OFF2 + NS*STAGE_BYTES)   // 186368
#define TILE_OFF(r, c) (((r) << 7) + ((uint32_t)(((c) ^ ((r) & 7)) & 7) << 4))

__global__ void __launch_bounds__(128, 1) lstm_kernel(const float* __restrict__ inp) {
    extern __shared__ char smem[];
    const uint32_t sb = s2u(smem);
    const int tid = threadIdx.x, lane = tid & 31, wid = tid >> 5;
    const int bn0 = blockIdx.x * 64, bm0 = blockIdx.y * 128;
    const int wm = (wid & 1) * 64, wn = (wid >> 1) * 32;
    float* sP1 = (float*)(smem + SP1_OFF);
    float* sP2 = (float*)(smem + SP2_OFF);
    float* Gs  = (float*)(smem + GS_OFF);
    unsigned goal = 0;

    // layer-static per-column epilogue params: [col][8] = {b, W, V0..V3, pad, pad}
    if (tid < 64) {
        int g = bn0 + tid;
        float *p1 = sP1 + tid * 8, *p2 = sP2 + tid * 8;
        p1[0] = g_b1p[g]; p1[1] = g_W1p[g];
        p2[0] = g_b2p[g]; p2[1] = 0.0f;
#pragma unroll
        for (int w = 0; w < 4; w++) {
            p1[2 + w] = g_V1p[w * GG + g];
            p2[2 + w] = g_V2p[w * GG + g];
        }
        p1[6] = p1[7] = p2[6] = p2[7] = 0.0f;
    }

    float creg1[16], creg2[16];
#pragma unroll
    for (int u = 0; u < 16; u++) { creg1[u] = 0.0f; creg2[u] = 0.0f; }

    float acc[4][4][4];

#pragma unroll 1
    for (int w = 0; w <= TT; w++) {
        // block list (each block = K=512 of hi/lo A,B pairs, 8 BK=64 chunks)
        const __nv_bfloat16 *pAh[3], *pAl[3], *pBh[3], *pBl[3];
        int nblk = 0;
        if (w > 0 && w < TT) {   // L1: h1[w-1] @ U1
            pAh[nblk] = g_h1h + (size_t)(w - 1) * BH; pAl[nblk] = g_h1l + (size_t)(w - 1) * BH;
            pBh[nblk] = g_U1h; pBl[nblk] = g_U1l; nblk++;
        }
        const int nch1 = nblk * 8;
        if (w >= 1) {
            int t2 = w - 1;
            if (t2 > 0) {        // L2 recurrent: h2[t2-1] @ U2
                pAh[nblk] = g_h2h + (size_t)(t2 - 1) * BH; pAl[nblk] = g_h2l + (size_t)(t2 - 1) * BH;
                pBh[nblk] = g_U2h; pBl[nblk] = g_U2l; nblk++;
            }
            // L2 input: h1[t2] @ W2
            pAh[nblk] = g_h1h + (size_t)t2 * BH; pAl[nblk] = g_h1l + (size_t)t2 * BH;
            pBh[nblk] = g_W2h; pBl[nblk] = g_W2l; nblk++;
        }
        const int ntot = nblk * 8;

        auto load_stage = [&](int chunk, int stg) {
            const int blk = chunk >> 3;
            const int kc = (chunk & 7) << 6;
            const uint32_t base = sb + STG_OFF2 + stg * STAGE_BYTES;
            const __nv_bfloat16 *Ah = pAh[blk], *Al = pAl[blk];
            const __nv_bfloat16 *Bh = pBh[blk], *Bl = pBl[blk];
#pragma unroll
            for (int i = 0; i < 8; i++) {      // A: 128 rows x 128B, hi+lo
                int e = tid + (i << 7); int r = e >> 3, q = e & 7;
                uint32_t off = TILE_OFF(r, q);
                size_t src = (size_t)(bm0 + r) * HH + kc + q * 8;
                cpasync16(base + OA_H + off, Ah + src);
                cpasync16(base + OA_L + off, Al + src);
            }
#pragma unroll
            for (int i = 0; i < 4; i++) {      // B: 64 rows x 128B, hi+lo
                int e = tid + (i << 7); int r = e >> 3, q = e & 7;
                uint32_t off = TILE_OFF(r, q);
                size_t src = (size_t)(bn0 + r) * HH + kc + q * 8;
                cpasync16(base + OB_H + off, Bh + src);
                cpasync16(base + OB_L + off, Bl + src);
            }
        };

        auto compute_chunk = [&](int stg) {
            const uint32_t st = sb + STG_OFF2 + stg * STAGE_BYTES;
#pragma unroll
            for (int s = 0; s < 4; s++) {
                const uint32_t ccol = (s << 1) + (lane >> 4);
                uint32_t ah[4][4], al[4][4], bh[2][4], bl[2][4];
#pragma unroll
                for (int mt = 0; mt < 4; mt++) {
                    int row = wm + mt * 16 + (lane & 15);
                    uint32_t off = TILE_OFF(row, ccol);
                    LDSM4(ah[mt][0], ah[mt][1], ah[mt][2], ah[mt][3], st + OA_H + off);
                    LDSM4(al[mt][0], al[mt][1], al[mt][2], al[mt][3], st + OA_L + off);
                }
#pragma unroll
                for (int np = 0; np < 2; np++) {
                    int row = wn + np * 16 + (lane & 15);
                    uint32_t off = TILE_OFF(row, ccol);
                    LDSM4(bh[np][0], bh[np][1], bh[np][2], bh[np][3], st + OB_H + off);
                    LDSM4(bl[np][0], bl[np][1], bl[np][2], bl[np][3], st + OB_L + off);
                }
#pragma unroll
                for (int mt = 0; mt < 4; mt++)
#pragma unroll
                    for (int nt = 0; nt < 4; nt++) {
                        uint32_t b0 = bh[nt >> 1][nt & 1], b1 = bh[nt >> 1][(nt & 1) + 2];
                        mma16816(acc[mt][nt], ah[mt], b0, b1);
                        mma16816(acc[mt][nt], al[mt], b0, b1);
                        mma16816(acc[mt][nt], ah[mt], bl[nt >> 1][nt & 1], bl[nt >> 1][(nt & 1) + 2]);
                    }
            }
        };

        auto run = [&](int from, int to) {
#pragma unroll 1
            for (int c = from; c < to; c++) {
                CP_WAIT(NS - 2);
                __syncthreads();
                int pf = c + NS - 1;
                if (pf < ntot) load_stage(pf, pf % NS);
                CP_COMMIT();
                compute_chunk(c % NS);
            }
        };

        auto epilogue = [&](int t, const float* sP, float (&creg)[16],
                            __nv_bfloat16* Hh, __nv_bfloat16* Hl) {
            __syncthreads();
#pragma unroll
            for (int mt = 0; mt < 4; mt++)
#pragma unroll
                for (int nt = 0; nt < 4; nt++) {
                    int row = wm + mt * 16 + (lane >> 2);
                    int col = wn + nt * 8 + (lane & 3) * 2;
                    *(float2*)(Gs + row * GSP + col)       = make_float2(acc[mt][nt][0], acc[mt][nt][1]);
                    *(float2*)(Gs + (row + 8) * GSP + col) = make_float2(acc[mt][nt][2], acc[mt][nt][3]);
                }
            __syncthreads();
            int b = bm0 + tid;
            const float* xr = inp + ((size_t)b * TT + t) * (WD + 1);
            float w0 = xr[0], w1 = xr[1], w2 = xr[2], w3 = xr[3], cnt = xr[4];
            __nv_bfloat16 oh[16], ol[16];
#pragma unroll
            for (int u = 0; u < 16; u++) {
                float4 g4 = *(float4*)(Gs + tid * GSP + u * 4);
                float gr[4] = {g4.x, g4.y, g4.z, g4.w};
                float gv[4];
#pragma unroll
                for (int q = 0; q < 4; q++) {
                    const float* p = sP + (u * 4 + q) * 8;
                    float4 p0 = *(const float4*)p;
                    float4 p1 = *(const float4*)(p + 4);
                    gv[q] = gr[q] + p0.x + cnt * p0.y + w0 * p0.z + w1 * p0.w + w2 * p1.x + w3 * p1.y;
                }
                float cc = sigf(gv[1]) * creg[u] + sigf(gv[0]) * tanhfast(gv[2]);
                float hv = sigf(gv[3]) * tanhfast(cc);
                creg[u] = cc;
                oh[u] = __float2bfloat16(hv);
                ol[u] = __float2bfloat16(hv - __bfloat162float(oh[u]));
            }
            size_t o = (size_t)b * HH + (bn0 >> 2);
            *(uint4*)(Hh + o)     = *(uint4*)oh;
            *(uint4*)(Hh + o + 8) = *(uint4*)(oh + 8);
            *(uint4*)(Hl + o)     = *(uint4*)ol;
            *(uint4*)(Hl + o + 8) = *(uint4*)(ol + 8);
        };

        // prologue prefetch (global chunk list)
#pragma unroll 1
        for (int j = 0; j < NS - 1 && j < ntot; j++) { load_stage(j, j); CP_COMMIT(); }

        // ---- L1 tile (t = w) ----
#pragma unroll
        for (int i = 0; i < 4; i++)
#pragma unroll
            for (int j = 0; j < 4; j++)
#pragma unroll
                for (int q = 0; q < 4; q++) acc[i][j][q] = 0.0f;
        run(0, nch1);
        if (w < TT)
            epilogue(w, sP1, creg1, g_h1h + (size_t)w * BH, g_h1l + (size_t)w * BH);

        // ---- L2 tile (t = w-1) ----
#pragma unroll
        for (int i = 0; i < 4; i++)
#pragma unroll
            for (int j = 0; j < 4; j++)
#pragma unroll
                for (int q = 0; q < 4; q++) acc[i][j][q] = 0.0f;
        run(nch1, ntot);
        if (w >= 1)
            epilogue(w - 1, sP2, creg2, g_h2h + (size_t)(w - 1) * BH, g_h2l + (size_t)(w - 1) * BH);

        // ---- device-wide barrier (all 128 CTAs co-resident at 1/SM) ----
        goal += NCTA;
        __syncthreads();
        if (tid == 0) {
            __threadfence();
            atomicAdd(&g_bar, 1u);
            unsigned v;
            do {
                asm volatile("ld.acquire.gpu.global.u32 %0, [%1];" : "=r"(v) : "l"(&g_bar));
                if (v < goal) __nanosleep(32);
            } while (v < goal);
        }
        __syncthreads();
    }
}

// ---------------- final FC ----------------
__global__ void fc_kernel(const float* __restrict__ fc_w, const float* __restrict__ fc_b,
                          float* __restrict__ out) {
    int warp = (blockIdx.x * blockDim.x + threadIdx.x) >> 5;
    int lane = threadIdx.x & 31;
    if (warp >= BB * TT) return;
    int b = warp / TT;
    int t = warp - b * TT;
    size_t base = (size_t)t * BH + (size_t)b * HH;
    float s = 0.0f;
#pragma unroll 4
    for (int j = lane; j < HH; j += 32)
        s += (__bfloat162float(g_h2h[base + j]) + __bfloat162float(g_h2l[base + j])) * fc_w[j];
#pragma unroll
    for (int o = 16; o; o >>= 1) s += __shfl_xor_sync(0xFFFFFFFFu, s, o);
    if (lane == 0) out[warp] = s + fc_b[0];
}

// ---------------- launch ----------------
extern "C" void kernel_launch(void* const* d_in, const int* in_sizes, int n_in,
                              void* d_out, int out_size) {
    const float* inputs = (const float*)d_in[0];
    const float* W1 = (const float*)d_in[1];
    const float* U1 = (const float*)d_in[2];
    const float* V1 = (const float*)d_in[3];
    const float* b1 = (const float*)d_in[4];
    const float* W2 = (const float*)d_in[5];
    const float* U2 = (const float*)d_in[6];
    const float* V2 = (const float*)d_in[7];
    const float* b2 = (const float*)d_in[8];
    const float* fc_w = (const float*)d_in[9];
    const float* fc_b = (const float*)d_in[10];
    float* out = (float*)d_out;

    cudaFuncSetAttribute(lstm_kernel, cudaFuncAttributeMaxDynamicSharedMemorySize, SMEM_TOTAL);

    prep_kernel<<<(HH * GG + 255) / 256, 256>>>(W1, U1, V1, b1, W2, U2, V2, b2);

    dim3 grid(GG / 64, BB / 128);   // (32, 4) = 128 CTAs, 1/SM, all co-resident
    lstm_kernel<<<grid, 128, SMEM_TOTAL>>>(inputs);

    int nwarps = BB * TT;
    fc_kernel<<<(nwarps * 32 + 255) / 256, 256>>>(fc_w, fc_b, out);
}

// round 14
// speedup vs baseline: 1.8172x; 1.8172x over previous
#include <cuda_runtime.h>
#include <cuda_bf16.h>
#include <math.h>
#include <stdint.h>

#define BB 512
#define TT 168
#define HH 512
#define GG 2048   // 4*H
#define WD 4
#define BH (BB*HH)

// ---------------- device scratch ----------------
__device__ __align__(256) __nv_bfloat16 g_h1h[TT*BH];
__device__ __align__(256) __nv_bfloat16 g_h1l[TT*BH];
__device__ __align__(256) __nv_bfloat16 g_h2h[TT*BH];
__device__ __align__(256) __nv_bfloat16 g_h2l[TT*BH];

// transposed + gate-interleaved weights, layout [n=2048][k=512] bf16 (hi/lo)
__device__ __align__(256) __nv_bfloat16 g_U1h[GG*HH], g_U1l[GG*HH];
__device__ __align__(256) __nv_bfloat16 g_U2h[GG*HH], g_U2l[GG*HH];
__device__ __align__(256) __nv_bfloat16 g_W2h[GG*HH], g_W2l[GG*HH];
__device__ float g_b1p[GG], g_b2p[GG], g_W1p[GG], g_V1p[WD*GG], g_V2p[WD*GG];
__device__ unsigned g_barg[4*32];   // one counter per bm-group, 128B apart

// ---------------- helpers ----------------
__device__ __forceinline__ uint32_t s2u(const void* p) {
    uint32_t a;
    asm("{ .reg .u64 t; cvta.to.shared.u64 t, %1; cvt.u32.u64 %0, t; }" : "=r"(a) : "l"(p));
    return a;
}
__device__ __forceinline__ void cpasync16(uint32_t dst, const void* src) {
    asm volatile("cp.async.cg.shared.global [%0], [%1], 16;" :: "r"(dst), "l"(src));
}
#define CP_COMMIT() asm volatile("cp.async.commit_group;")
#define CP_WAIT(n)  asm volatile("cp.async.wait_group %0;" :: "n"(n))
#define LDSM4(r0,r1,r2,r3,addr) \
    asm volatile("ldmatrix.sync.aligned.m8n8.x4.shared.b16 {%0,%1,%2,%3}, [%4];" \
        : "=r"(r0),"=r"(r1),"=r"(r2),"=r"(r3) : "r"(addr))

__device__ __forceinline__ void mma16816(float* c, const uint32_t* a, uint32_t b0, uint32_t b1) {
    asm volatile("mma.sync.aligned.m16n8k16.row.col.f32.bf16.bf16.f32 "
        "{%0,%1,%2,%3}, {%4,%5,%6,%7}, {%8,%9}, {%0,%1,%2,%3};"
        : "+f"(c[0]), "+f"(c[1]), "+f"(c[2]), "+f"(c[3])
        : "r"(a[0]), "r"(a[1]), "r"(a[2]), "r"(a[3]), "r"(b0), "r"(b1));
}

__device__ __forceinline__ float sigf(float x) { return 1.0f / (1.0f + __expf(-x)); }
__device__ __forceinline__ float tanhfast(float x) { return 1.0f - 2.0f / (1.0f + __expf(2.0f * x)); }

// ---------------- prologue: permute + transpose + bf16 hi/lo split ----------------
__global__ void prep_kernel(const float* __restrict__ W1, const float* __restrict__ U1,
                            const float* __restrict__ V1, const float* __restrict__ b1,
                            const float* __restrict__ W2, const float* __restrict__ U2,
                            const float* __restrict__ V2, const float* __restrict__ b2) {
    int idx = blockIdx.x * blockDim.x + threadIdx.x;
    if (idx < 4 * 32) g_barg[idx] = 0u;
    if (idx >= HH * GG) return;
    int k  = idx >> 11;
    int gp = idx & (GG - 1);
    int go = (gp & 3) * HH + (gp >> 2);
    int dst = gp * HH + k;

    float u1 = U1[k * GG + go];
    __nv_bfloat16 h = __float2bfloat16(u1);
    g_U1h[dst] = h; g_U1l[dst] = __float2bfloat16(u1 - __bfloat162float(h));
    float u2 = U2[k * GG + go];
    h = __float2bfloat16(u2);
    g_U2h[dst] = h; g_U2l[dst] = __float2bfloat16(u2 - __bfloat162float(h));
    float w2 = W2[k * GG + go];
    h = __float2bfloat16(w2);
    g_W2h[dst] = h; g_W2l[dst] = __float2bfloat16(w2 - __bfloat162float(h));

    if (k == 0) {
        g_W1p[gp] = W1[go];
        g_b1p[gp] = b1[go];
        g_b2p[gp] = b2[go];
#pragma unroll
        for (int w = 0; w < WD; w++) {
            g_V1p[w * GG + gp] = V1[w * GG + go];
            g_V2p[w * GG + gp] = V2[w * GG + go];
        }
    }
}

// ---------------- persistent LSTM kernel: weights resident in smem ----------------
// CTA tile M=128 (batch) x N=64 (gates), BK=64. Grid (32, 4) = 128 CTAs, 256 threads.
// U-weights (64 cols x 512 k, hi+lo = 128KB) stay in smem for the whole layer.
#define PAR_OFF 0                       // 2048 B: per-column params
#define W_OFF 2048                      // 131072 B: persistent weights (8 tiles hi, 8 tiles lo)
#define W_LO 65536                      //   lo tiles at W_OFF + W_LO
#define A_OFF 133120                    // 2 stages x 32768 (hi 16K + lo 16K)
#define A_STAGE 32768
#define B_OFF 198656                    // 2 stages x 16384 (hi 8K + lo 8K)
#define B_STAGE 16384
#define SMEM_TOTAL 231424
#define GSP 68
#define TILE_OFF(r, c) (((r) << 7) + ((uint32_t)(((c) ^ ((r) & 7)) & 7) << 4))

__global__ void __launch_bounds__(256, 1) lstm_kernel(const float* __restrict__ inp) {
    extern __shared__ char smem[];
    const uint32_t sb = s2u(smem);
    const int tid = threadIdx.x, lane = tid & 31, wid = tid >> 5;
    const int bn0 = blockIdx.x * 64, bm0 = blockIdx.y * 128;
    const int wm = (wid & 3) * 32, wn = (wid >> 2) * 32;
    float* sP = (float*)(smem + PAR_OFF);
    float* Gs = (float*)(smem + A_OFF);     // aliased over A stream (used only in epilogue)
    unsigned* barp = &g_barg[blockIdx.y * 32];
    unsigned goal = 0;

#pragma unroll 1
    for (int layer = 1; layer <= 2; layer++) {
        // ---- per-column epilogue params ----
        if (tid < 64) {
            int g = bn0 + tid;
            float* p = sP + tid * 8;
            if (layer == 1) {
                p[0] = g_b1p[g]; p[1] = g_W1p[g];
#pragma unroll
                for (int w = 0; w < 4; w++) p[2 + w] = g_V1p[w * GG + g];
            } else {
                p[0] = g_b2p[g]; p[1] = 0.0f;
#pragma unroll
                for (int w = 0; w < 4; w++) p[2 + w] = g_V2p[w * GG + g];
            }
            p[6] = 0.0f; p[7] = 0.0f;
        }
        // ---- load persistent U weights (hi+lo, 8 chunk tiles each) ----
        {
            const __nv_bfloat16* Uh = (layer == 1) ? g_U1h : g_U2h;
            const __nv_bfloat16* Ul = (layer == 1) ? g_U1l : g_U2l;
#pragma unroll
            for (int i = 0; i < 16; i++) {
                int e = tid + (i << 8);
                int tile = e >> 9, rem = e & 511;
                int r = rem >> 3, q = rem & 7;
                uint32_t off = tile * 8192 + TILE_OFF(r, q);
                size_t src = (size_t)(bn0 + r) * HH + tile * 64 + q * 8;
                cpasync16(sb + W_OFF + off, Uh + src);
                cpasync16(sb + W_OFF + W_LO + off, Ul + src);
            }
            CP_COMMIT();
            CP_WAIT(0);
            __syncthreads();
        }

        __nv_bfloat16* Hh = (layer == 1) ? g_h1h : g_h2h;
        __nv_bfloat16* Hl = (layer == 1) ? g_h1l : g_h2l;

        float creg[8];
#pragma unroll
        for (int u = 0; u < 8; u++) creg[u] = 0.0f;

#pragma unroll 1
        for (int t = 0; t < TT; t++) {
            // block list: up to 2 blocks of K=512 (8 BK=64 chunks each)
            const __nv_bfloat16 *bAh[2], *bAl[2];
            bool bStr[2] = {false, false};
            int nblk = 0;
            if (t > 0) {   // recurrent: h_prev @ U (persistent B)
                bAh[nblk] = Hh + (size_t)(t - 1) * BH;
                bAl[nblk] = Hl + (size_t)(t - 1) * BH;
                bStr[nblk] = false; nblk++;
            }
            if (layer == 2) {   // input: h1[t] @ W2 (streamed B)
                bAh[nblk] = g_h1h + (size_t)t * BH;
                bAl[nblk] = g_h1l + (size_t)t * BH;
                bStr[nblk] = true; nblk++;
            }
            const int nch = nblk * 8;

            float acc[2][4][4];
#pragma unroll
            for (int i = 0; i < 2; i++)
#pragma unroll
                for (int j = 0; j < 4; j++)
#pragma unroll
                    for (int q = 0; q < 4; q++) acc[i][j][q] = 0.0f;

            if (nch) {
                auto load_chunk = [&](int c) {
                    const int blk = c >> 3, kc = (c & 7) << 6;
                    const __nv_bfloat16 *Ah = bAh[blk], *Al = bAl[blk];
                    uint32_t ab = sb + A_OFF + (c & 1) * A_STAGE;
#pragma unroll
                    for (int i = 0; i < 4; i++) {       // A: 128 rows x 128B, hi+lo
                        int e = tid + (i << 8); int r = e >> 3, q = e & 7;
                        uint32_t off = TILE_OFF(r, q);
                        size_t src = (size_t)(bm0 + r) * HH + kc + q * 8;
                        cpasync16(ab + off, Ah + src);
                        cpasync16(ab + 16384 + off, Al + src);
                    }
                    if (bStr[blk]) {                    // B: 64 rows x 128B, hi+lo (W2)
                        uint32_t bb = sb + B_OFF + (c & 1) * B_STAGE;
#pragma unroll
                        for (int i = 0; i < 2; i++) {
                            int e = tid + (i << 8); int r = e >> 3, q = e & 7;
                            uint32_t off = TILE_OFF(r, q);
                            size_t src = (size_t)(bn0 + r) * HH + kc + q * 8;
                            cpasync16(bb + off, g_W2h + src);
                            cpasync16(bb + 8192 + off, g_W2l + src);
                        }
                    }
                };

                load_chunk(0);
                CP_COMMIT();
#pragma unroll 1
                for (int c = 0; c < nch; c++) {
                    if (c + 1 < nch) load_chunk(c + 1);
                    CP_COMMIT();
                    CP_WAIT(1);
                    __syncthreads();
                    const uint32_t aHi = sb + A_OFF + (c & 1) * A_STAGE;
                    const uint32_t aLo = aHi + 16384;
                    uint32_t bHi, bLo;
                    if (bStr[c >> 3]) {
                        bHi = sb + B_OFF + (c & 1) * B_STAGE; bLo = bHi + 8192;
                    } else {
                        bHi = sb + W_OFF + (c & 7) * 8192;    bLo = bHi + W_LO;
                    }
#pragma unroll
                    for (int s = 0; s < 4; s++) {
                        const uint32_t ccol = (s << 1) + (lane >> 4);
                        uint32_t ah[2][4], al[2][4], bh[2][4], bl[2][4];
#pragma unroll
                        for (int mt = 0; mt < 2; mt++) {
                            int row = wm + mt * 16 + (lane & 15);
                            uint32_t off = TILE_OFF(row, ccol);
                            LDSM4(ah[mt][0], ah[mt][1], ah[mt][2], ah[mt][3], aHi + off);
                            LDSM4(al[mt][0], al[mt][1], al[mt][2], al[mt][3], aLo + off);
                        }
#pragma unroll
                        for (int np = 0; np < 2; np++) {
                            int row = wn + np * 16 + (lane & 15);
                            uint32_t off = TILE_OFF(row, ccol);
                            LDSM4(bh[np][0], bh[np][1], bh[np][2], bh[np][3], bHi + off);
                            LDSM4(bl[np][0], bl[np][1], bl[np][2], bl[np][3], bLo + off);
                        }
#pragma unroll
                        for (int mt = 0; mt < 2; mt++)
#pragma unroll
                            for (int nt = 0; nt < 4; nt++) {
                                uint32_t b0 = bh[nt >> 1][nt & 1], b1 = bh[nt >> 1][(nt & 1) + 2];
                                mma16816(acc[mt][nt], ah[mt], b0, b1);
                                mma16816(acc[mt][nt], al[mt], b0, b1);
                                mma16816(acc[mt][nt], ah[mt], bl[nt >> 1][nt & 1], bl[nt >> 1][(nt & 1) + 2]);
                            }
                    }
                    __syncthreads();
                }
            }

            // ---- epilogue: stage gates, fused LSTM pointwise ----
            __syncthreads();
#pragma unroll
            for (int mt = 0; mt < 2; mt++)
#pragma unroll
                for (int nt = 0; nt < 4; nt++) {
                    int row = wm + mt * 16 + (lane >> 2);
                    int col = wn + nt * 8 + (lane & 3) * 2;
                    *(float2*)(Gs + row * GSP + col)       = make_float2(acc[mt][nt][0], acc[mt][nt][1]);
                    *(float2*)(Gs + (row + 8) * GSP + col) = make_float2(acc[mt][nt][2], acc[mt][nt][3]);
                }
            __syncthreads();

            {
                int bl_ = tid & 127;        // batch row within tile
                int half = tid >> 7;        // 0/1: units 0-7 / 8-15
                int b = bm0 + bl_;
                const float* xr = inp + ((size_t)b * TT + t) * (WD + 1);
                float w0 = xr[0], w1 = xr[1], w2 = xr[2], w3 = xr[3], cnt = xr[4];
                __nv_bfloat16 oh[8], ol[8];
#pragma unroll
                for (int u = 0; u < 8; u++) {
                    int jl = half * 8 + u;
                    float4 g4 = *(float4*)(Gs + bl_ * GSP + jl * 4);
                    float gr[4] = {g4.x, g4.y, g4.z, g4.w};
                    float gv[4];
#pragma unroll
                    for (int q = 0; q < 4; q++) {
                        const float* p = sP + (jl * 4 + q) * 8;
                        float4 p0 = *(const float4*)p;
                        float4 p1 = *(const float4*)(p + 4);
                        gv[q] = gr[q] + p0.x + cnt * p0.y + w0 * p0.z + w1 * p0.w + w2 * p1.x + w3 * p1.y;
                    }
                    float cc = sigf(gv[1]) * creg[u] + sigf(gv[0]) * tanhfast(gv[2]);
                    float hv = sigf(gv[3]) * tanhfast(cc);
                    creg[u] = cc;
                    oh[u] = __float2bfloat16(hv);
                    ol[u] = __float2bfloat16(hv - __bfloat162float(oh[u]));
                }
                size_t o = (size_t)t * BH + (size_t)b * HH + (bn0 >> 2) + half * 8;
                *(uint4*)(Hh + o) = *(uint4*)oh;
                *(uint4*)(Hl + o) = *(uint4*)ol;
            }

            // ---- bm-group barrier (32 CTAs sharing this batch slice) ----
            goal += 32;
            __syncthreads();
            if (tid == 0) {
                __threadfence();
                atomicAdd(barp, 1u);
                unsigned v;
                do {
                    asm volatile("ld.acquire.gpu.global.u32 %0, [%1];" : "=r"(v) : "l"(barp));
                    if (v < goal) __nanosleep(32);
                } while (v < goal);
            }
            __syncthreads();
        }
    }
}

// ---------------- final FC ----------------
__global__ void fc_kernel(const float* __restrict__ fc_w, const float* __restrict__ fc_b,
                          float* __restrict__ out) {
    int warp = (blockIdx.x * blockDim.x + threadIdx.x) >> 5;
    int lane = threadIdx.x & 31;
    if (warp >= BB * TT) return;
    int b = warp / TT;
    int t = warp - b * TT;
    size_t base = (size_t)t * BH + (size_t)b * HH;
    float s = 0.0f;
#pragma unroll 4
    for (int j = lane; j < HH; j += 32)
        s += (__bfloat162float(g_h2h[base + j]) + __bfloat162float(g_h2l[base + j])) * fc_w[j];
#pragma unroll
    for (int o = 16; o; o >>= 1) s += __shfl_xor_sync(0xFFFFFFFFu, s, o);
    if (lane == 0) out[warp] = s + fc_b[0];
}

// ---------------- launch ----------------
extern "C" void kernel_launch(void* const* d_in, const int* in_sizes, int n_in,
                              void* d_out, int out_size) {
    const float* inputs = (const float*)d_in[0];
    const float* W1 = (const float*)d_in[1];
    const float* U1 = (const float*)d_in[2];
    const float* V1 = (const float*)d_in[3];
    const float* b1 = (const float*)d_in[4];
    const float* W2 = (const float*)d_in[5];
    const float* U2 = (const float*)d_in[6];
    const float* V2 = (const float*)d_in[7];
    const float* b2 = (const float*)d_in[8];
    const float* fc_w = (const float*)d_in[9];
    const float* fc_b = (const float*)d_in[10];
    float* out = (float*)d_out;

    cudaFuncSetAttribute(lstm_kernel, cudaFuncAttributeMaxDynamicSharedMemorySize, SMEM_TOTAL);

    prep_kernel<<<(HH * GG + 255) / 256, 256>>>(W1, U1, V1, b1, W2, U2, V2, b2);

    dim3 grid(GG / 64, BB / 128);   // (32, 4) = 128 CTAs, 1/SM, all co-resident
    lstm_kernel<<<grid, 256, SMEM_TOTAL>>>(inputs);

    int nwarps = BB * TT;
    fc_kernel<<<(nwarps * 32 + 255) / 256, 256>>>(fc_w, fc_b, out);
}

// round 16
// speedup vs baseline: 2.5222x; 1.3880x over previous
#include <cuda_runtime.h>
#include <cuda_fp16.h>
#include <math.h>
#include <stdint.h>

#define BB 512
#define TT 168
#define HH 512
#define GG 2048   // 4*H
#define WD 4
#define BH (BB*HH)

// ---------------- device scratch ----------------
__device__ __align__(256) __half g_h1[TT*BH];   // layer-1 hidden, single fp16
__device__ __align__(256) __half g_h2[TT*BH];   // layer-2 hidden, single fp16

// transposed + gate-interleaved weights, layout [n=2048][k=512] fp16 hi/lo
__device__ __align__(256) __half g_U1h[GG*HH], g_U1l[GG*HH];
__device__ __align__(256) __half g_U2h[GG*HH], g_U2l[GG*HH];
__device__ __align__(256) __half g_W2h[GG*HH], g_W2l[GG*HH];
__device__ float g_b1p[GG], g_b2p[GG], g_W1p[GG], g_V1p[WD*GG], g_V2p[WD*GG];
__device__ unsigned g_barg[4*32];   // one counter per bm-group, 128B apart

// ---------------- helpers ----------------
__device__ __forceinline__ uint32_t s2u(const void* p) {
    uint32_t a;
    asm("{ .reg .u64 t; cvta.to.shared.u64 t, %1; cvt.u32.u64 %0, t; }" : "=r"(a) : "l"(p));
    return a;
}
__device__ __forceinline__ void cpasync16(uint32_t dst, const void* src) {
    asm volatile("cp.async.cg.shared.global [%0], [%1], 16;" :: "r"(dst), "l"(src));
}
#define CP_COMMIT() asm volatile("cp.async.commit_group;")
#define CP_WAIT(n)  asm volatile("cp.async.wait_group %0;" :: "n"(n))
#define LDSM4(r0,r1,r2,r3,addr) \
    asm volatile("ldmatrix.sync.aligned.m8n8.x4.shared.b16 {%0,%1,%2,%3}, [%4];" \
        : "=r"(r0),"=r"(r1),"=r"(r2),"=r"(r3) : "r"(addr))

__device__ __forceinline__ void mma16816(float* c, const uint32_t* a, uint32_t b0, uint32_t b1) {
    asm volatile("mma.sync.aligned.m16n8k16.row.col.f32.f16.f16.f32 "
        "{%0,%1,%2,%3}, {%4,%5,%6,%7}, {%8,%9}, {%0,%1,%2,%3};"
        : "+f"(c[0]), "+f"(c[1]), "+f"(c[2]), "+f"(c[3])
        : "r"(a[0]), "r"(a[1]), "r"(a[2]), "r"(a[3]), "r"(b0), "r"(b1));
}

__device__ __forceinline__ float sigf(float x) { return 1.0f / (1.0f + __expf(-x)); }
__device__ __forceinline__ float tanhfast(float x) { return 1.0f - 2.0f / (1.0f + __expf(2.0f * x)); }

// ---------------- prologue: permute + transpose + fp16 hi/lo split ----------------
__global__ void prep_kernel(const float* __restrict__ W1, const float* __restrict__ U1,
                            const float* __restrict__ V1, const float* __restrict__ b1,
                            const float* __restrict__ W2, const float* __restrict__ U2,
                            const float* __restrict__ V2, const float* __restrict__ b2) {
    int idx = blockIdx.x * blockDim.x + threadIdx.x;
    if (idx < 4 * 32) g_barg[idx] = 0u;
    if (idx >= HH * GG) return;
    int k  = idx >> 11;
    int gp = idx & (GG - 1);
    int go = (gp & 3) * HH + (gp >> 2);
    int dst = gp * HH + k;

    float u1 = U1[k * GG + go];
    __half h = __float2half(u1);
    g_U1h[dst] = h; g_U1l[dst] = __float2half(u1 - __half2float(h));
    float u2 = U2[k * GG + go];
    h = __float2half(u2);
    g_U2h[dst] = h; g_U2l[dst] = __float2half(u2 - __half2float(h));
    float w2 = W2[k * GG + go];
    h = __float2half(w2);
    g_W2h[dst] = h; g_W2l[dst] = __float2half(w2 - __half2float(h));

    if (k == 0) {
        g_W1p[gp] = W1[go];
        g_b1p[gp] = b1[go];
        g_b2p[gp] = b2[go];
#pragma unroll
        for (int w = 0; w < WD; w++) {
            g_V1p[w * GG + gp] = V1[w * GG + go];
            g_V2p[w * GG + gp] = V2[w * GG + go];
        }
    }
}

// ---------------- persistent LSTM kernel: weights resident, fp16 2-term ----------------
// CTA tile M=128 (batch) x N=64 (gates), BK=64. Grid (32, 4) = 128 CTAs, 256 threads.
#define NS 3
#define PAR_OFF 0                       // 2048 B
#define W_OFF 2048                      // 131072 B: U hi (8 tiles x 8192) + lo at +65536
#define W_LO 65536
#define A_OFF 133120                    // 3 stages x 16384 (A single fp16)
#define A_STAGE 16384
#define B_OFF 182272                    // 3 stages x 16384 (W2 hi 8K + lo 8K)
#define B_STAGE 16384
#define SMEM_TOTAL 231424
#define GSP 68
#define TILE_OFF(r, c) (((r) << 7) + ((uint32_t)(((c) ^ ((r) & 7)) & 7) << 4))

__global__ void __launch_bounds__(256, 1) lstm_kernel(const float* __restrict__ inp) {
    extern __shared__ char smem[];
    const uint32_t sb = s2u(smem);
    const int tid = threadIdx.x, lane = tid & 31, wid = tid >> 5;
    const int bn0 = blockIdx.x * 64, bm0 = blockIdx.y * 128;
    const int wm = (wid & 3) * 32, wn = (wid >> 2) * 32;
    float* sP = (float*)(smem + PAR_OFF);
    float* Gs = (float*)(smem + A_OFF);     // aliased over A stream (epilogue only)
    unsigned* barp = &g_barg[blockIdx.y * 32];
    unsigned goal = 0;

#pragma unroll 1
    for (int layer = 1; layer <= 2; layer++) {
        if (tid < 64) {
            int g = bn0 + tid;
            float* p = sP + tid * 8;
            if (layer == 1) {
                p[0] = g_b1p[g]; p[1] = g_W1p[g];
#pragma unroll
                for (int w = 0; w < 4; w++) p[2 + w] = g_V1p[w * GG + g];
            } else {
                p[0] = g_b2p[g]; p[1] = 0.0f;
#pragma unroll
                for (int w = 0; w < 4; w++) p[2 + w] = g_V2p[w * GG + g];
            }
            p[6] = 0.0f; p[7] = 0.0f;
        }
        // ---- load persistent U weights (hi+lo, 8 chunk tiles each) ----
        {
            const __half* Uh = (layer == 1) ? g_U1h : g_U2h;
            const __half* Ul = (layer == 1) ? g_U1l : g_U2l;
#pragma unroll
            for (int i = 0; i < 16; i++) {
                int e = tid + (i << 8);
                int tile = e >> 9, rem = e & 511;
                int r = rem >> 3, q = rem & 7;
                uint32_t off = tile * 8192 + TILE_OFF(r, q);
                size_t src = (size_t)(bn0 + r) * HH + tile * 64 + q * 8;
                cpasync16(sb + W_OFF + off, Uh + src);
                cpasync16(sb + W_OFF + W_LO + off, Ul + src);
            }
            CP_COMMIT();
            CP_WAIT(0);
            __syncthreads();
        }

        __half* Hc = (layer == 1) ? g_h1 : g_h2;

        float creg[8];
#pragma unroll
        for (int u = 0; u < 8; u++) creg[u] = 0.0f;

#pragma unroll 1
        for (int t = 0; t < TT; t++) {
            const __half* bA[2];
            bool bStr[2] = {false, false};
            int nblk = 0;
            if (t > 0) {                 // recurrent: h_prev @ U (persistent B)
                bA[nblk] = Hc + (size_t)(t - 1) * BH;
                bStr[nblk] = false; nblk++;
            }
            if (layer == 2) {            // input: h1[t] @ W2 (streamed B)
                bA[nblk] = g_h1 + (size_t)t * BH;
                bStr[nblk] = true; nblk++;
            }
            const int nch = nblk * 8;

            float acc[2][4][4];
#pragma unroll
            for (int i = 0; i < 2; i++)
#pragma unroll
                for (int j = 0; j < 4; j++)
#pragma unroll
                    for (int q = 0; q < 4; q++) acc[i][j][q] = 0.0f;

            if (nch) {
                auto load_chunk = [&](int c, int stg) {
                    const int blk = c >> 3, kc = (c & 7) << 6;
                    const __half* Ah = bA[blk];
                    uint32_t ab = sb + A_OFF + stg * A_STAGE;
#pragma unroll
                    for (int i = 0; i < 4; i++) {       // A: 128 rows x 128B (full 16KB)
                        int e = tid + (i << 8); int r = e >> 3, q = e & 7;
                        uint32_t off = TILE_OFF(r, q);
                        cpasync16(ab + off, Ah + (size_t)(bm0 + r) * HH + kc + q * 8);
                    }
                    if (bStr[blk]) {                    // B: 64 rows x 128B, hi+lo (W2)
                        uint32_t bb = sb + B_OFF + stg * B_STAGE;
#pragma unroll
                        for (int i = 0; i < 2; i++) {
                            int e = tid + (i << 8); int r = e >> 3, q = e & 7;
                            uint32_t off = TILE_OFF(r, q);
                            size_t src = (size_t)(bn0 + r) * HH + kc + q * 8;
                            cpasync16(bb + off, g_W2h + src);
                            cpasync16(bb + 8192 + off, g_W2l + src);
                        }
                    }
                };

#pragma unroll 1
                for (int j = 0; j < NS - 1 && j < nch; j++) { load_chunk(j, j); CP_COMMIT(); }

#pragma unroll 1
                for (int c = 0; c < nch; c++) {
                    CP_WAIT(NS - 2);
                    __syncthreads();
                    int pf = c + NS - 1;
                    if (pf < nch) load_chunk(pf, pf % NS);
                    CP_COMMIT();
                    const uint32_t aBase = sb + A_OFF + (c % NS) * A_STAGE;
                    uint32_t bHi, bLo;
                    if (bStr[c >> 3]) {
                        bHi = sb + B_OFF + (c % NS) * B_STAGE; bLo = bHi + 8192;
                    } else {
                        bHi = sb + W_OFF + (c & 7) * 8192;     bLo = bHi + W_LO;
                    }
#pragma unroll
                    for (int s = 0; s < 4; s++) {
                        const uint32_t ccol = (s << 1) + (lane >> 4);
                        uint32_t a[2][4], bh[2][4], bl[2][4];
#pragma unroll
                        for (int mt = 0; mt < 2; mt++) {
                            int row = wm + mt * 16 + (lane & 15);
                            LDSM4(a[mt][0], a[mt][1], a[mt][2], a[mt][3],
                                  aBase + TILE_OFF(row, ccol));
                        }
#pragma unroll
                        for (int np = 0; np < 2; np++) {
                            int row = wn + np * 16 + (lane & 15);
                            uint32_t off = TILE_OFF(row, ccol);
                            LDSM4(bh[np][0], bh[np][1], bh[np][2], bh[np][3], bHi + off);
                            LDSM4(bl[np][0], bl[np][1], bl[np][2], bl[np][3], bLo + off);
                        }
#pragma unroll
                        for (int mt = 0; mt < 2; mt++)
#pragma unroll
                            for (int nt = 0; nt < 4; nt++) {
                                mma16816(acc[mt][nt], a[mt],
                                         bh[nt >> 1][nt & 1], bh[nt >> 1][(nt & 1) + 2]);
                                mma16816(acc[mt][nt], a[mt],
                                         bl[nt >> 1][nt & 1], bl[nt >> 1][(nt & 1) + 2]);
                            }
                    }
                }
            }

            // ---- epilogue: stage gates, fused LSTM pointwise ----
            __syncthreads();
#pragma unroll
            for (int mt = 0; mt < 2; mt++)
#pragma unroll
                for (int nt = 0; nt < 4; nt++) {
                    int row = wm + mt * 16 + (lane >> 2);
                    int col = wn + nt * 8 + (lane & 3) * 2;
                    *(float2*)(Gs + row * GSP + col)       = make_float2(acc[mt][nt][0], acc[mt][nt][1]);
                    *(float2*)(Gs + (row + 8) * GSP + col) = make_float2(acc[mt][nt][2], acc[mt][nt][3]);
                }
            __syncthreads();

            {
                int bl_ = tid & 127;
                int half = tid >> 7;
                int b = bm0 + bl_;
                const float* xr = inp + ((size_t)b * TT + t) * (WD + 1);
                float w0 = xr[0], w1 = xr[1], w2 = xr[2], w3 = xr[3], cnt = xr[4];
                __half oh[8];
#pragma unroll
                for (int u = 0; u < 8; u++) {
                    int jl = half * 8 + u;
                    float4 g4 = *(float4*)(Gs + bl_ * GSP + jl * 4);
                    float gr[4] = {g4.x, g4.y, g4.z, g4.w};
                    float gv[4];
#pragma unroll
                    for (int q = 0; q < 4; q++) {
                        const float* p = sP + (jl * 4 + q) * 8;
                        float4 p0 = *(const float4*)p;
                        float4 p1 = *(const float4*)(p + 4);
                        gv[q] = gr[q] + p0.x + cnt * p0.y + w0 * p0.z + w1 * p0.w + w2 * p1.x + w3 * p1.y;
                    }
                    float cc = sigf(gv[1]) * creg[u] + sigf(gv[0]) * tanhfast(gv[2]);
                    float hv = sigf(gv[3]) * tanhfast(cc);
                    creg[u] = cc;
                    oh[u] = __float2half(hv);
                }
                size_t o = (size_t)t * BH + (size_t)b * HH + (bn0 >> 2) + half * 8;
                *(uint4*)(Hc + o) = *(uint4*)oh;
            }

            // ---- bm-group barrier (32 CTAs sharing this batch slice) ----
            goal += 32;
            __syncthreads();
            if (tid == 0) {
                __threadfence();
                atomicAdd(barp, 1u);
                unsigned v;
                do {
                    asm volatile("ld.acquire.gpu.global.u32 %0, [%1];" : "=r"(v) : "l"(barp));
                    if (v < goal) __nanosleep(32);
                } while (v < goal);
            }
            __syncthreads();
        }
    }
}

// ---------------- final FC ----------------
__global__ void fc_kernel(const float* __restrict__ fc_w, const float* __restrict__ fc_b,
                          float* __restrict__ out) {
    int warp = (blockIdx.x * blockDim.x + threadIdx.x) >> 5;
    int lane = threadIdx.x & 31;
    if (warp >= BB * TT) return;
    int b = warp / TT;
    int t = warp - b * TT;
    size_t base = (size_t)t * BH + (size_t)b * HH;
    float s = 0.0f;
#pragma unroll 4
    for (int j = lane; j < HH; j += 32)
        s += __half2float(g_h2[base + j]) * fc_w[j];
#pragma unroll
    for (int o = 16; o; o >>= 1) s += __shfl_xor_sync(0xFFFFFFFFu, s, o);
    if (lane == 0) out[warp] = s + fc_b[0];
}

// ---------------- launch ----------------
extern "C" void kernel_launch(void* const* d_in, const int* in_sizes, int n_in,
                              void* d_out, int out_size) {
    const float* inputs = (const float*)d_in[0];
    const float* W1 = (const float*)d_in[1];
    const float* U1 = (const float*)d_in[2];
    const float* V1 = (const float*)d_in[3];
    const float* b1 = (const float*)d_in[4];
    const float* W2 = (const float*)d_in[5];
    const float* U2 = (const float*)d_in[6];
    const float* V2 = (const float*)d_in[7];
    const float* b2 = (const float*)d_in[8];
    const float* fc_w = (const float*)d_in[9];
    const float* fc_b = (const float*)d_in[10];
    float* out = (float*)d_out;

    cudaFuncSetAttribute(lstm_kernel, cudaFuncAttributeMaxDynamicSharedMemorySize, SMEM_TOTAL);

    prep_kernel<<<(HH * GG + 255) / 256, 256>>>(W1, U1, V1, b1, W2, U2, V2, b2);

    dim3 grid(GG / 64, BB / 128);   // (32, 4) = 128 CTAs, 1/SM, all co-resident
    lstm_kernel<<<grid, 256, SMEM_TOTAL>>>(inputs);

    int nwarps = BB * TT;
    fc_kernel<<<(nwarps * 32 + 255) / 256, 256>>>(fc_w, fc_b, out);
}

// round 17
// speedup vs baseline: 2.5779x; 1.0220x over previous
#include <cuda_runtime.h>
#include <cuda_fp16.h>
#include <math.h>
#include <stdint.h>

#define BB 512
#define TT 168
#define HH 512
#define GG 2048   // 4*H
#define WD 4
#define BH (BB*HH)

// ---------------- device scratch ----------------
__device__ __align__(256) __half g_h1[TT*BH];
__device__ __align__(256) __half g_h2[TT*BH];
__device__ __align__(256) float g_pre2[(size_t)TT*BB*GG];   // h1 @ W2, all t

// transposed + gate-interleaved weights, layout [n=2048][k=512] fp16 hi/lo
__device__ __align__(256) __half g_U1h[GG*HH], g_U1l[GG*HH];
__device__ __align__(256) __half g_U2h[GG*HH], g_U2l[GG*HH];
__device__ __align__(256) __half g_W2h[GG*HH], g_W2l[GG*HH];
__device__ float g_b1p[GG], g_b2p[GG], g_W1p[GG], g_V1p[WD*GG], g_V2p[WD*GG];
__device__ unsigned g_barL[2][128];   // per-layer, per-bm-group counters (32-padded)

// ---------------- helpers ----------------
__device__ __forceinline__ uint32_t s2u(const void* p) {
    uint32_t a;
    asm("{ .reg .u64 t; cvta.to.shared.u64 t, %1; cvt.u32.u64 %0, t; }" : "=r"(a) : "l"(p));
    return a;
}
__device__ __forceinline__ void cpasync16(uint32_t dst, const void* src) {
    asm volatile("cp.async.cg.shared.global [%0], [%1], 16;" :: "r"(dst), "l"(src));
}
#define CP_COMMIT() asm volatile("cp.async.commit_group;")
#define CP_WAIT(n)  asm volatile("cp.async.wait_group %0;" :: "n"(n))
#define LDSM4(r0,r1,r2,r3,addr) \
    asm volatile("ldmatrix.sync.aligned.m8n8.x4.shared.b16 {%0,%1,%2,%3}, [%4];" \
        : "=r"(r0),"=r"(r1),"=r"(r2),"=r"(r3) : "r"(addr))

__device__ __forceinline__ void mma16816(float* c, const uint32_t* a, uint32_t b0, uint32_t b1) {
    asm volatile("mma.sync.aligned.m16n8k16.row.col.f32.f16.f16.f32 "
        "{%0,%1,%2,%3}, {%4,%5,%6,%7}, {%8,%9}, {%0,%1,%2,%3};"
        : "+f"(c[0]), "+f"(c[1]), "+f"(c[2]), "+f"(c[3])
        : "r"(a[0]), "r"(a[1]), "r"(a[2]), "r"(a[3]), "r"(b0), "r"(b1));
}

__device__ __forceinline__ float sigf(float x) { return 1.0f / (1.0f + __expf(-x)); }
__device__ __forceinline__ float tanhfast(float x) { return 1.0f - 2.0f / (1.0f + __expf(2.0f * x)); }

// ---------------- shared smem layout (serial + w2 kernels) ----------------
#define NS 3
#define PAR_OFF 0                       // 2048 B
#define W_OFF 2048                      // 131072 B: hi 8 tiles x 8192 + lo at +65536
#define W_LO 65536
#define A_OFF 133120                    // 3 stages x 16384
#define A_STAGE 16384
#define SMEM_TOTAL 182272
#define GSP 68
#define TILE_OFF(r, c) (((r) << 7) + ((uint32_t)(((c) ^ ((r) & 7)) & 7) << 4))

// ---------------- prologue: permute + transpose + fp16 hi/lo split ----------------
__global__ void prep_kernel(const float* __restrict__ W1, const float* __restrict__ U1,
                            const float* __restrict__ V1, const float* __restrict__ b1,
                            const float* __restrict__ W2, const float* __restrict__ U2,
                            const float* __restrict__ V2, const float* __restrict__ b2) {
    int idx = blockIdx.x * blockDim.x + threadIdx.x;
    if (idx < 256) ((unsigned*)g_barL)[idx] = 0u;
    if (idx >= HH * GG) return;
    int k  = idx >> 11;
    int gp = idx & (GG - 1);
    int go = (gp & 3) * HH + (gp >> 2);
    int dst = gp * HH + k;

    float u1 = U1[k * GG + go];
    __half h = __float2half(u1);
    g_U1h[dst] = h; g_U1l[dst] = __float2half(u1 - __half2float(h));
    float u2 = U2[k * GG + go];
    h = __float2half(u2);
    g_U2h[dst] = h; g_U2l[dst] = __float2half(u2 - __half2float(h));
    float w2 = W2[k * GG + go];
    h = __float2half(w2);
    g_W2h[dst] = h; g_W2l[dst] = __float2half(w2 - __half2float(h));

    if (k == 0) {
        g_W1p[gp] = W1[go];
        g_b1p[gp] = b1[go];
        g_b2p[gp] = b2[go];
#pragma unroll
        for (int w = 0; w < WD; w++) {
            g_V1p[w * GG + gp] = V1[w * GG + go];
            g_V2p[w * GG + gp] = V2[w * GG + go];
        }
    }
}

// ---------------- serial LSTM kernel (recurrent term only) ----------------
// CTA tile M=128 x N=64, BK=64. Grid (32, 4) = 128 CTAs, 256 threads, U resident.
template <int LAYER>
__global__ void __launch_bounds__(256, 1) lstm_kernel(const float* __restrict__ inp) {
    extern __shared__ char smem[];
    const uint32_t sb = s2u(smem);
    const int tid = threadIdx.x, lane = tid & 31, wid = tid >> 5;
    const int bn0 = blockIdx.x * 64, bm0 = blockIdx.y * 128;
    const int wm = (wid & 3) * 32, wn = (wid >> 2) * 32;
    float* sP = (float*)(smem + PAR_OFF);
    float* Gs = (float*)(smem + A_OFF);
    unsigned* barp = &g_barL[LAYER - 1][blockIdx.y * 32];
    unsigned goal = 0;

    if (tid < 64) {
        int g = bn0 + tid;
        float* p = sP + tid * 8;
        if (LAYER == 1) {
            p[0] = g_b1p[g]; p[1] = g_W1p[g];
#pragma unroll
            for (int w = 0; w < 4; w++) p[2 + w] = g_V1p[w * GG + g];
        } else {
            p[0] = g_b2p[g]; p[1] = 0.0f;
#pragma unroll
            for (int w = 0; w < 4; w++) p[2 + w] = g_V2p[w * GG + g];
        }
        p[6] = 0.0f; p[7] = 0.0f;
    }
    // ---- load persistent U weights (hi+lo, 8 chunk tiles each) ----
    {
        const __half* Uh = (LAYER == 1) ? g_U1h : g_U2h;
        const __half* Ul = (LAYER == 1) ? g_U1l : g_U2l;
#pragma unroll
        for (int i = 0; i < 16; i++) {
            int e = tid + (i << 8);
            int tile = e >> 9, rem = e & 511;
            int r = rem >> 3, q = rem & 7;
            uint32_t off = tile * 8192 + TILE_OFF(r, q);
            size_t src = (size_t)(bn0 + r) * HH + tile * 64 + q * 8;
            cpasync16(sb + W_OFF + off, Uh + src);
            cpasync16(sb + W_OFF + W_LO + off, Ul + src);
        }
        CP_COMMIT();
        CP_WAIT(0);
        __syncthreads();
    }

    __half* Hc = (LAYER == 1) ? g_h1 : g_h2;

    float creg[8];
#pragma unroll
    for (int u = 0; u < 8; u++) creg[u] = 0.0f;

#pragma unroll 1
    for (int t = 0; t < TT; t++) {
        const int nch = (t > 0) ? 8 : 0;
        const __half* Ah = Hc + (size_t)(t - 1) * BH;

        float acc[2][4][4];
#pragma unroll
        for (int i = 0; i < 2; i++)
#pragma unroll
            for (int j = 0; j < 4; j++)
#pragma unroll
                for (int q = 0; q < 4; q++) acc[i][j][q] = 0.0f;

        if (nch) {
            auto load_chunk = [&](int c, int stg) {
                const int kc = c << 6;
                uint32_t ab = sb + A_OFF + stg * A_STAGE;
#pragma unroll
                for (int i = 0; i < 4; i++) {     // A: 128 rows x 128B
                    int e = tid + (i << 8); int r = e >> 3, q = e & 7;
                    cpasync16(ab + TILE_OFF(r, q),
                              Ah + (size_t)(bm0 + r) * HH + kc + q * 8);
                }
            };

#pragma unroll 1
            for (int j = 0; j < NS - 1; j++) { load_chunk(j, j); CP_COMMIT(); }

#pragma unroll 1
            for (int c = 0; c < nch; c++) {
                CP_WAIT(NS - 2);
                __syncthreads();
                int pf = c + NS - 1;
                if (pf < nch) load_chunk(pf, pf % NS);
                CP_COMMIT();
                const uint32_t aBase = sb + A_OFF + (c % NS) * A_STAGE;
                const uint32_t bHi = sb + W_OFF + (c & 7) * 8192;
                const uint32_t bLo = bHi + W_LO;
#pragma unroll
                for (int s = 0; s < 4; s++) {
                    const uint32_t ccol = (s << 1) + (lane >> 4);
                    uint32_t a[2][4], bh[2][4], bl[2][4];
#pragma unroll
                    for (int mt = 0; mt < 2; mt++) {
                        int row = wm + mt * 16 + (lane & 15);
                        LDSM4(a[mt][0], a[mt][1], a[mt][2], a[mt][3],
                              aBase + TILE_OFF(row, ccol));
                    }
#pragma unroll
                    for (int np = 0; np < 2; np++) {
                        int row = wn + np * 16 + (lane & 15);
                        uint32_t off = TILE_OFF(row, ccol);
                        LDSM4(bh[np][0], bh[np][1], bh[np][2], bh[np][3], bHi + off);
                        LDSM4(bl[np][0], bl[np][1], bl[np][2], bl[np][3], bLo + off);
                    }
#pragma unroll
                    for (int mt = 0; mt < 2; mt++)
#pragma unroll
                        for (int nt = 0; nt < 4; nt++) {
                            mma16816(acc[mt][nt], a[mt],
                                     bh[nt >> 1][nt & 1], bh[nt >> 1][(nt & 1) + 2]);
                            mma16816(acc[mt][nt], a[mt],
                                     bl[nt >> 1][nt & 1], bl[nt >> 1][(nt & 1) + 2]);
                        }
                }
            }
        }

        // ---- epilogue: stage gates, fused LSTM pointwise ----
        __syncthreads();
#pragma unroll
        for (int mt = 0; mt < 2; mt++)
#pragma unroll
            for (int nt = 0; nt < 4; nt++) {
                int row = wm + mt * 16 + (lane >> 2);
                int col = wn + nt * 8 + (lane & 3) * 2;
                *(float2*)(Gs + row * GSP + col)       = make_float2(acc[mt][nt][0], acc[mt][nt][1]);
                *(float2*)(Gs + (row + 8) * GSP + col) = make_float2(acc[mt][nt][2], acc[mt][nt][3]);
            }
        __syncthreads();

        {
            int bl_ = tid & 127;
            int half = tid >> 7;
            int b = bm0 + bl_;
            const float* xr = inp + ((size_t)b * TT + t) * (WD + 1);
            float w0 = xr[0], w1 = xr[1], w2 = xr[2], w3 = xr[3], cnt = xr[4];
            const float* pr = (LAYER == 2)
                ? g_pre2 + ((size_t)t * BB + b) * GG + bn0 : (const float*)0;
            __half oh[8];
#pragma unroll
            for (int u = 0; u < 8; u++) {
                int jl = half * 8 + u;
                float4 g4 = *(float4*)(Gs + bl_ * GSP + jl * 4);
                float gr[4] = {g4.x, g4.y, g4.z, g4.w};
                if (LAYER == 2) {
                    float4 p4 = *(const float4*)(pr + jl * 4);
                    gr[0] += p4.x; gr[1] += p4.y; gr[2] += p4.z; gr[3] += p4.w;
                }
                float gv[4];
#pragma unroll
                for (int q = 0; q < 4; q++) {
                    const float* p = sP + (jl * 4 + q) * 8;
                    float4 p0 = *(const float4*)p;
                    float4 p1 = *(const float4*)(p + 4);
                    gv[q] = gr[q] + p0.x + cnt * p0.y + w0 * p0.z + w1 * p0.w + w2 * p1.x + w3 * p1.y;
                }
                float cc = sigf(gv[1]) * creg[u] + sigf(gv[0]) * tanhfast(gv[2]);
                float hv = sigf(gv[3]) * tanhfast(cc);
                creg[u] = cc;
                oh[u] = __float2half(hv);
            }
            size_t o = (size_t)t * BH + (size_t)b * HH + (bn0 >> 2) + half * 8;
            *(uint4*)(Hc + o) = *(uint4*)oh;
        }

        // ---- bm-group barrier ----
        goal += 32;
        __syncthreads();
        if (tid == 0) {
            __threadfence();
            atomicAdd(barp, 1u);
            unsigned v;
            do {
                asm volatile("ld.acquire.gpu.global.u32 %0, [%1];" : "=r"(v) : "l"(barp));
                if (v < goal) __nanosleep(32);
            } while (v < goal);
        }
        __syncthreads();
    }
}

// ---------------- phase B: pre2 = h1 @ W2 (big parallel GEMM) ----------------
// Grid (32, 42): bn slice x t-group of 4. W2 slice resident; flat 128-chunk loop
// over (tt, bm, kc) = 4 x 4 x 8 with the same pipeline as the serial kernel.
#define TGRP 4
__global__ void __launch_bounds__(256, 1) w2_kernel() {
    extern __shared__ char smem[];
    const uint32_t sb = s2u(smem);
    const int tid = threadIdx.x, lane = tid & 31, wid = tid >> 5;
    const int bn0 = blockIdx.x * 64;
    const int t0 = blockIdx.y * TGRP;
    const int wm = (wid & 3) * 32, wn = (wid >> 2) * 32;

    // ---- load W2 slice resident ----
#pragma unroll
    for (int i = 0; i < 16; i++) {
        int e = tid + (i << 8);
        int tile = e >> 9, rem = e & 511;
        int r = rem >> 3, q = rem & 7;
        uint32_t off = tile * 8192 + TILE_OFF(r, q);
        size_t src = (size_t)(bn0 + r) * HH + tile * 64 + q * 8;
        cpasync16(sb + W_OFF + off, g_W2h + src);
        cpasync16(sb + W_OFF + W_LO + off, g_W2l + src);
    }
    CP_COMMIT();
    CP_WAIT(0);
    __syncthreads();

    const int NCH = TGRP * 4 * 8;   // 128 chunks

    auto load_chunk = [&](int c) {
        const int t = t0 + (c >> 5);
        const int bm0 = ((c >> 3) & 3) * 128;
        const int kc = (c & 7) << 6;
        uint32_t ab = sb + A_OFF + (c % NS) * A_STAGE;
        const __half* Ah = g_h1 + (size_t)t * BH;
#pragma unroll
        for (int i = 0; i < 4; i++) {
            int e = tid + (i << 8); int r = e >> 3, q = e & 7;
            cpasync16(ab + TILE_OFF(r, q), Ah + (size_t)(bm0 + r) * HH + kc + q * 8);
        }
    };

    float acc[2][4][4];
#pragma unroll
    for (int i = 0; i < 2; i++)
#pragma unroll
        for (int j = 0; j < 4; j++)
#pragma unroll
            for (int q = 0; q < 4; q++) acc[i][j][q] = 0.0f;

#pragma unroll 1
    for (int j = 0; j < NS - 1; j++) { load_chunk(j); CP_COMMIT(); }

#pragma unroll 1
    for (int c = 0; c < NCH; c++) {
        CP_WAIT(NS - 2);
        __syncthreads();
        int pf = c + NS - 1;
        if (pf < NCH) load_chunk(pf);
        CP_COMMIT();
        const uint32_t aBase = sb + A_OFF + (c % NS) * A_STAGE;
        const uint32_t bHi = sb + W_OFF + (c & 7) * 8192;
        const uint32_t bLo = bHi + W_LO;
#pragma unroll
        for (int s = 0; s < 4; s++) {
            const uint32_t ccol = (s << 1) + (lane >> 4);
            uint32_t a[2][4], bh[2][4], bl[2][4];
#pragma unroll
            for (int mt = 0; mt < 2; mt++) {
                int row = wm + mt * 16 + (lane & 15);
                LDSM4(a[mt][0], a[mt][1], a[mt][2], a[mt][3], aBase + TILE_OFF(row, ccol));
            }
#pragma unroll
            for (int np = 0; np < 2; np++) {
                int row = wn + np * 16 + (lane & 15);
                uint32_t off = TILE_OFF(row, ccol);
                LDSM4(bh[np][0], bh[np][1], bh[np][2], bh[np][3], bHi + off);
                LDSM4(bl[np][0], bl[np][1], bl[np][2], bl[np][3], bLo + off);
            }
#pragma unroll
            for (int mt = 0; mt < 2; mt++)
#pragma unroll
                for (int nt = 0; nt < 4; nt++) {
                    mma16816(acc[mt][nt], a[mt],
                             bh[nt >> 1][nt & 1], bh[nt >> 1][(nt & 1) + 2]);
                    mma16816(acc[mt][nt], a[mt],
                             bl[nt >> 1][nt & 1], bl[nt >> 1][(nt & 1) + 2]);
                }
        }
        if ((c & 7) == 7) {
            // store this (t, bm) group's pre2 tile and reset acc
            const int t = t0 + (c >> 5);
            const int bm0 = ((c >> 3) & 3) * 128;
            float* dst = g_pre2 + (size_t)t * BB * GG;
#pragma unroll
            for (int mt = 0; mt < 2; mt++)
#pragma unroll
                for (int nt = 0; nt < 4; nt++) {
                    int row = bm0 + wm + mt * 16 + (lane >> 2);
                    int col = bn0 + wn + nt * 8 + (lane & 3) * 2;
                    *(float2*)(dst + (size_t)row * GG + col) =
                        make_float2(acc[mt][nt][0], acc[mt][nt][1]);
                    *(float2*)(dst + (size_t)(row + 8) * GG + col) =
                        make_float2(acc[mt][nt][2], acc[mt][nt][3]);
                    acc[mt][nt][0] = acc[mt][nt][1] = acc[mt][nt][2] = acc[mt][nt][3] = 0.0f;
                }
        }
    }
}

// ---------------- final FC ----------------
__global__ void fc_kernel(const float* __restrict__ fc_w, const float* __restrict__ fc_b,
                          float* __restrict__ out) {
    int warp = (blockIdx.x * blockDim.x + threadIdx.x) >> 5;
    int lane = threadIdx.x & 31;
    if (warp >= BB * TT) return;
    int b = warp / TT;
    int t = warp - b * TT;
    size_t base = (size_t)t * BH + (size_t)b * HH;
    float s = 0.0f;
#pragma unroll 4
    for (int j = lane; j < HH; j += 32)
        s += __half2float(g_h2[base + j]) * fc_w[j];
#pragma unroll
    for (int o = 16; o; o >>= 1) s += __shfl_xor_sync(0xFFFFFFFFu, s, o);
    if (lane == 0) out[warp] = s + fc_b[0];
}

// ---------------- launch ----------------
extern "C" void kernel_launch(void* const* d_in, const int* in_sizes, int n_in,
                              void* d_out, int out_size) {
    const float* inputs = (const float*)d_in[0];
    const float* W1 = (const float*)d_in[1];
    const float* U1 = (const float*)d_in[2];
    const float* V1 = (const float*)d_in[3];
    const float* b1 = (const float*)d_in[4];
    const float* W2 = (const float*)d_in[5];
    const float* U2 = (const float*)d_in[6];
    const float* V2 = (const float*)d_in[7];
    const float* b2 = (const float*)d_in[8];
    const float* fc_w = (const float*)d_in[9];
    const float* fc_b = (const float*)d_in[10];
    float* out = (float*)d_out;

    cudaFuncSetAttribute(lstm_kernel<1>, cudaFuncAttributeMaxDynamicSharedMemorySize, SMEM_TOTAL);
    cudaFuncSetAttribute(lstm_kernel<2>, cudaFuncAttributeMaxDynamicSharedMemorySize, SMEM_TOTAL);
    cudaFuncSetAttribute(w2_kernel, cudaFuncAttributeMaxDynamicSharedMemorySize, SMEM_TOTAL);

    prep_kernel<<<(HH * GG + 255) / 256, 256>>>(W1, U1, V1, b1, W2, U2, V2, b2);

    dim3 grid(GG / 64, BB / 128);   // (32, 4) = 128 CTAs
    lstm_kernel<1><<<grid, 256, SMEM_TOTAL>>>(inputs);
    dim3 gw2(GG / 64, TT / TGRP);   // (32, 42)
    w2_kernel<<<gw2, 256, SMEM_TOTAL>>>();
    lstm_kernel<2><<<grid, 256, SMEM_TOTAL>>>(inputs);

    int nwarps = BB * TT;
    fc_kernel<<<(nwarps * 32 + 255) / 256, 256>>>(fc_w, fc_b, out);
}